// round 1
// baseline (speedup 1.0000x reference)
#include <cuda_runtime.h>
#include <cstdint>

// Problem constants
#define NB   8
#define CIN  16
#define LL   1024
#define DDIM 7
#define SZ   112     // CIN*DDIM
#define HH   16
#define DP   8       // padded head dim

// Scratch for Q/K/V in [n][h][l][8] layout (padded head dim), 4MB each.
__device__ float g_q[NB * HH * LL * DP];
__device__ float g_k[NB * HH * LL * DP];
__device__ float g_v[NB * HH * LL * DP];

// ---------------- f32x2 packed helpers (Blackwell FFMA2 path) ----------------
using u64 = unsigned long long;

__device__ __forceinline__ u64 pk2(float lo, float hi) {
    u64 r; asm("mov.b64 %0,{%1,%2};" : "=l"(r) : "f"(lo), "f"(hi)); return r;
}
__device__ __forceinline__ u64 dup2(float v) {
    u64 r; asm("mov.b64 %0,{%1,%1};" : "=l"(r) : "f"(v)); return r;
}
__device__ __forceinline__ void up2(u64 v, float& lo, float& hi) {
    asm("mov.b64 {%0,%1},%2;" : "=f"(lo), "=f"(hi) : "l"(v));
}
__device__ __forceinline__ void up2u(u64 v, unsigned& lo, unsigned& hi) {
    asm("mov.b64 {%0,%1},%2;" : "=r"(lo), "=r"(hi) : "l"(v));
}
__device__ __forceinline__ u64 pk2u(unsigned lo, unsigned hi) {
    u64 r; asm("mov.b64 %0,{%1,%2};" : "=l"(r) : "r"(lo), "r"(hi)); return r;
}
__device__ __forceinline__ u64 fma2(u64 a, u64 b, u64 c) {
    u64 d; asm("fma.rn.f32x2 %0,%1,%2,%3;" : "=l"(d) : "l"(a), "l"(b), "l"(c)); return d;
}
__device__ __forceinline__ u64 mul2(u64 a, u64 b) {
    u64 d; asm("mul.rn.f32x2 %0,%1,%2;" : "=l"(d) : "l"(a), "l"(b)); return d;
}
__device__ __forceinline__ u64 add2(u64 a, u64 b) {
    u64 d; asm("add.rn.f32x2 %0,%1,%2;" : "=l"(d) : "l"(a), "l"(b)); return d;
}

// ---------------- Kernel 1: fused transpose + QKV projection ----------------
// grid = (64, 3): blockIdx.x -> (n, l-tile of 128), blockIdx.y -> which of Wq/Wk/Wv.
// Each block: xs[128][113] tile of xf (transpose fused into load),
// ws[112][113] full weight matrix; 16x16 threads, 8x7 register tiles.
#define LDS_X 113
#define LDS_W 113
#define GEMM_SMEM ((128 * LDS_X + SZ * LDS_W) * 4)

__global__ void __launch_bounds__(256)
qkv_gemm(const float* __restrict__ x,
         const float* __restrict__ Wq, const float* __restrict__ bq,
         const float* __restrict__ Wk, const float* __restrict__ bk,
         const float* __restrict__ Wv, const float* __restrict__ bv)
{
    extern __shared__ float sm[];
    float* xs = sm;                 // [128][LDS_X]
    float* ws = sm + 128 * LDS_X;   // [112][LDS_W]

    const int tid = threadIdx.x;
    const int m = blockIdx.y;
    const float* W = (m == 0) ? Wq : ((m == 1) ? Wk : Wv);
    const float* b = (m == 0) ? bq : ((m == 1) ? bk : bv);
    float* og = (m == 0) ? g_q : ((m == 1) ? g_k : g_v);

    const int n  = blockIdx.x >> 3;
    const int l0 = (blockIdx.x & 7) << 7;

    // Load W [112][112] row-major into padded smem
    for (int i = tid; i < SZ * SZ; i += 256)
        ws[(i / SZ) * LDS_W + (i % SZ)] = W[i];

    // Load x tile, transposing [c][l][dd] -> xs[l][c*7+dd]. Each c-chunk is
    // 896 contiguous floats in gmem -> coalesced.
    const float* xb = x + ((size_t)n * CIN * LL + l0) * DDIM;
    for (int i = tid; i < CIN * 128 * DDIM; i += 256) {
        int c = i / (128 * DDIM);
        int r = i - c * (128 * DDIM);
        float v = xb[(size_t)c * LL * DDIM + r];
        int l = r / DDIM;
        int dd = r - l * DDIM;
        xs[l * LDS_X + c * DDIM + dd] = v;
    }
    __syncthreads();

    const int tx = tid & 15;        // col group: head index
    const int ty = tid >> 4;        // row group
    const int c0 = tx * 7;
    const int r0 = ty * 8;

    float acc[8][7];
#pragma unroll
    for (int j = 0; j < 7; ++j) {
        float bb = __ldg(&b[c0 + j]);
#pragma unroll
        for (int i = 0; i < 8; ++i) acc[i][j] = bb;
    }

#pragma unroll 2
    for (int f = 0; f < SZ; ++f) {
        float xv[8];
        float wv[7];
#pragma unroll
        for (int i = 0; i < 8; ++i) xv[i] = xs[(r0 + i) * LDS_X + f];
#pragma unroll
        for (int j = 0; j < 7; ++j) wv[j] = ws[(c0 + j) * LDS_W + f];
#pragma unroll
        for (int i = 0; i < 8; ++i)
#pragma unroll
            for (int j = 0; j < 7; ++j)
                acc[i][j] = fmaf(xv[i], wv[j], acc[i][j]);
    }

    // cols c0..c0+6 are exactly head tx, dd = j. Store [n][h][l][8], pad dd=7 with 0.
    float* op = og + (((size_t)n * HH + tx) * LL + l0 + r0) * DP;
#pragma unroll
    for (int i = 0; i < 8; ++i) {
#pragma unroll
        for (int j = 0; j < 7; ++j) op[i * DP + j] = acc[i][j];
        op[i * DP + 7] = 0.0f;
    }
}

// ---------------- Kernel 2: fused softmax attention per (n, h) ----------------
// grid = 128 blocks (one per n*16+h), 256 threads, each thread owns 4 query rows
// packed as two f32x2 pairs. K/V head tiles live in smem (broadcast LDS.128).
// Softmax without max-subtraction (scores bounded |s| < ~2 after /32 scale),
// exp via FMA-pipe exp2 polynomial (no MUFU).
#define ATT_SMEM (2 * LL * DP * 4)   // 64 KB

__global__ void __launch_bounds__(256)
attn_kernel(float* __restrict__ out)
{
    extern __shared__ float sm[];
    float* ks = sm;            // [1024][8]
    float* vs = sm + LL * DP;  // [1024][8]

    const int tid = threadIdx.x;
    const int bh = blockIdx.x;     // n*16 + h

    // Cooperative load of K and V head tiles (float4, fully coalesced)
    {
        const float4* k4 = (const float4*)(g_k + (size_t)bh * LL * DP);
        const float4* v4 = (const float4*)(g_v + (size_t)bh * LL * DP);
        float4* ks4 = (float4*)ks;
        float4* vs4 = (float4*)vs;
        for (int i = tid; i < LL * DP / 4; i += 256) {
            ks4[i] = k4[i];
            vs4[i] = v4[i];
        }
    }

    // Load this thread's 4 query rows, pack into row-pairs
    const int r0 = tid * 4;
    const float* qg = g_q + ((size_t)bh * LL + r0) * DP;
    u64 q0[7], q1[7];
    {
        float4 a0 = *(const float4*)(qg + 0);
        float4 a1 = *(const float4*)(qg + 4);
        float4 b0 = *(const float4*)(qg + 8);
        float4 b1 = *(const float4*)(qg + 12);
        float4 c0 = *(const float4*)(qg + 16);
        float4 c1 = *(const float4*)(qg + 20);
        float4 d0 = *(const float4*)(qg + 24);
        float4 d1 = *(const float4*)(qg + 28);
        q0[0] = pk2(a0.x, b0.x); q0[1] = pk2(a0.y, b0.y); q0[2] = pk2(a0.z, b0.z);
        q0[3] = pk2(a0.w, b0.w); q0[4] = pk2(a1.x, b1.x); q0[5] = pk2(a1.y, b1.y);
        q0[6] = pk2(a1.z, b1.z);
        q1[0] = pk2(c0.x, d0.x); q1[1] = pk2(c0.y, d0.y); q1[2] = pk2(c0.z, d0.z);
        q1[3] = pk2(c0.w, d0.w); q1[4] = pk2(c1.x, d1.x); q1[5] = pk2(c1.y, d1.y);
        q1[6] = pk2(c1.z, d1.z);
    }
    __syncthreads();

    // exp(s/32) = 2^(s * log2e/32); magic-round + deg-4 poly + exponent insert
    const u64 SC   = dup2(0.04508422002778011f);   // log2(e)/32
    const u64 MAG  = dup2(12582912.0f);            // 1.5 * 2^23
    const u64 NMAG = dup2(-12582912.0f);
    const u64 NONE = dup2(-1.0f);
    const u64 P4   = dup2(0.009618129107f);
    const u64 P3   = dup2(0.055504108664f);
    const u64 P2c  = dup2(0.240226506959f);
    const u64 P1   = dup2(0.693147180560f);
    const u64 ONE  = dup2(1.0f);

    u64 acc0[7], acc1[7];
    u64 S0 = dup2(0.0f), S1 = dup2(0.0f);
#pragma unroll
    for (int j = 0; j < 7; ++j) { acc0[j] = S0; acc1[j] = S0; }

#pragma unroll 2
    for (int key = 0; key < LL; ++key) {
        float4 ka = *(const float4*)&ks[key * DP];
        float4 kb = *(const float4*)&ks[key * DP + 4];
        u64 k0 = dup2(ka.x), k1 = dup2(ka.y), k2 = dup2(ka.z), k3 = dup2(ka.w);
        u64 k4 = dup2(kb.x), k5 = dup2(kb.y), k6 = dup2(kb.z);

        u64 s0 = mul2(q0[0], k0);
        u64 s1 = mul2(q1[0], k0);
        s0 = fma2(q0[1], k1, s0); s1 = fma2(q1[1], k1, s1);
        s0 = fma2(q0[2], k2, s0); s1 = fma2(q1[2], k2, s1);
        s0 = fma2(q0[3], k3, s0); s1 = fma2(q1[3], k3, s1);
        s0 = fma2(q0[4], k4, s0); s1 = fma2(q1[4], k4, s1);
        s0 = fma2(q0[5], k5, s0); s1 = fma2(q1[5], k5, s1);
        s0 = fma2(q0[6], k6, s0); s1 = fma2(q1[6], k6, s1);

        // packed fast exp
        u64 y0 = mul2(s0, SC),  y1 = mul2(s1, SC);
        u64 t0 = add2(y0, MAG), t1 = add2(y1, MAG);
        u64 i0 = add2(t0, NMAG), i1 = add2(t1, NMAG);
        u64 f0 = fma2(i0, NONE, y0), f1 = fma2(i1, NONE, y1);
        u64 p0 = fma2(P4, f0, P3);
        u64 p1 = fma2(P4, f1, P3);
        p0 = fma2(p0, f0, P2c); p1 = fma2(p1, f1, P2c);
        p0 = fma2(p0, f0, P1);  p1 = fma2(p1, f1, P1);
        p0 = fma2(p0, f0, ONE); p1 = fma2(p1, f1, ONE);
        {
            unsigned tl, th, pl, ph;
            up2u(t0, tl, th); up2u(p0, pl, ph);
            pl += tl << 23; ph += th << 23;
            p0 = pk2u(pl, ph);
            up2u(t1, tl, th); up2u(p1, pl, ph);
            pl += tl << 23; ph += th << 23;
            p1 = pk2u(pl, ph);
        }
        S0 = add2(S0, p0);
        S1 = add2(S1, p1);

        float4 va = *(const float4*)&vs[key * DP];
        float4 vb = *(const float4*)&vs[key * DP + 4];
        u64 v0 = dup2(va.x), v1 = dup2(va.y), v2 = dup2(va.z), v3 = dup2(va.w);
        u64 v4 = dup2(vb.x), v5 = dup2(vb.y), v6 = dup2(vb.z);

        acc0[0] = fma2(p0, v0, acc0[0]); acc1[0] = fma2(p1, v0, acc1[0]);
        acc0[1] = fma2(p0, v1, acc0[1]); acc1[1] = fma2(p1, v1, acc1[1]);
        acc0[2] = fma2(p0, v2, acc0[2]); acc1[2] = fma2(p1, v2, acc1[2]);
        acc0[3] = fma2(p0, v3, acc0[3]); acc1[3] = fma2(p1, v3, acc1[3]);
        acc0[4] = fma2(p0, v4, acc0[4]); acc1[4] = fma2(p1, v4, acc1[4]);
        acc0[5] = fma2(p0, v5, acc0[5]); acc1[5] = fma2(p1, v5, acc1[5]);
        acc0[6] = fma2(p0, v6, acc0[6]); acc1[6] = fma2(p1, v6, acc1[6]);
    }

    // Normalize and store (output layout [N,H,L,7])
    float sA, sB, sC, sD;
    up2(S0, sA, sB);
    up2(S1, sC, sD);
    float iA = 1.0f / sA, iB = 1.0f / sB, iC = 1.0f / sC, iD = 1.0f / sD;

    float* op = out + ((size_t)bh * LL + r0) * DDIM;
#pragma unroll
    for (int j = 0; j < 7; ++j) {
        float a, b, c, d;
        up2(acc0[j], a, b);
        up2(acc1[j], c, d);
        op[j]            = a * iA;
        op[DDIM + j]     = b * iB;
        op[2 * DDIM + j] = c * iC;
        op[3 * DDIM + j] = d * iD;
    }
}

// ---------------- launch ----------------
extern "C" void kernel_launch(void* const* d_in, const int* in_sizes, int n_in,
                              void* d_out, int out_size)
{
    const float* x  = (const float*)d_in[0];
    const float* Wq = (const float*)d_in[1];
    const float* bq = (const float*)d_in[2];
    const float* Wk = (const float*)d_in[3];
    const float* bk = (const float*)d_in[4];
    const float* Wv = (const float*)d_in[5];
    const float* bv = (const float*)d_in[6];

    cudaFuncSetAttribute(qkv_gemm, cudaFuncAttributeMaxDynamicSharedMemorySize, GEMM_SMEM);
    cudaFuncSetAttribute(attn_kernel, cudaFuncAttributeMaxDynamicSharedMemorySize, ATT_SMEM);

    qkv_gemm<<<dim3(64, 3), 256, GEMM_SMEM>>>(x, Wq, bq, Wk, bk, Wv, bv);
    attn_kernel<<<128, 256, ATT_SMEM>>>((float*)d_out);
}